// round 6
// baseline (speedup 1.0000x reference)
#include <cuda_runtime.h>
#include <cuda_bf16.h>
#include <cstdint>

#define Lseq 256
#define Qd   21
#define Mseq 8192
#define KN   5376           // L*Q (output N dimension)
#define MT   128
#define NT   128
#define KC   64             // K chunk width: 3 j's * 21 + 1 pad col
#define NCH2 85             // max chunks (j up to 254)
#define K2   (NCH2 * KC)    // 5440 padded K extent of B
#define NTILES (KN / NT)    // 42
#define MTILES (Mseq / MT)  // 64

// ---------------- device scratch ----------------
__device__ __nv_bfloat16 g_B[(size_t)KN * K2];         // B[(i,a)][c*64 + jj*21 + k], causal-masked
__device__ float         g_contrib[(size_t)Mseq * KN]; // contrib[b][i*21+a]
__device__ double        g_acc[4];                     // 0: wsum 1: sum w*ll 2: sum Jm^2 3: sum h^2

// ---------------- helpers ----------------
__device__ __forceinline__ uint32_t smem_u32(const void* p) {
    uint32_t r;
    asm("{ .reg .u64 t; cvta.to.shared.u64 t, %1; cvt.u32.u64 %0, t; }" : "=r"(r) : "l"(p));
    return r;
}
__device__ __forceinline__ double block_sum(double v) {
    __shared__ double sh[32];
    int lane = threadIdx.x & 31, w = threadIdx.x >> 5;
    #pragma unroll
    for (int o = 16; o; o >>= 1) v += __shfl_down_sync(0xffffffffu, v, o);
    if (lane == 0) sh[w] = v;
    __syncthreads();
    double r = 0.0;
    if (w == 0) {
        int nw = blockDim.x >> 5;
        r = (lane < nw) ? sh[lane] : 0.0;
        #pragma unroll
        for (int o = 16; o; o >>= 1) r += __shfl_down_sync(0xffffffffu, r, o);
    }
    __syncthreads();
    return r;
}

#define LDSM_X4(r0, r1, r2, r3, addr)                                            \
    asm volatile("ldmatrix.sync.aligned.m8n8.x4.shared.b16 {%0,%1,%2,%3}, [%4];" \
                 : "=r"(r0), "=r"(r1), "=r"(r2), "=r"(r3) : "r"(addr))

#define MMA16816(d, a, b0, b1)                                                          \
    asm volatile("mma.sync.aligned.m16n8k16.row.col.f32.bf16.bf16.f32 "                 \
                 "{%0,%1,%2,%3},{%4,%5,%6,%7},{%8,%9},{%0,%1,%2,%3};"                   \
                 : "+f"(d[0]), "+f"(d[1]), "+f"(d[2]), "+f"(d[3])                       \
                 : "r"(a[0]), "r"(a[1]), "r"(a[2]), "r"(a[3]), "r"(b0), "r"(b1))

#define CP_ASYNC16(dst, src)                                                             \
    asm volatile("cp.async.cg.shared.global [%0], [%1], 16;" :: "r"(dst), "l"(src))
#define CP_COMMIT() asm volatile("cp.async.commit_group;" ::: "memory")
#define CP_WAIT1()  asm volatile("cp.async.wait_group 1;" ::: "memory")

// causal chunk bound: chunks of 3 j's needed for the N-tile containing tile_x.
__device__ __forceinline__ int chunk_bound_for_tile(int tile_x) {
    int imax = (tile_x * NT + NT - 1) / Qd;
    if (imax > Lseq - 1) imax = Lseq - 1;
    return (imax + 2) / 3;           // ceil(imax/3), max 85, min 2
}

// ---------------- small kernels ----------------
__global__ void zero_acc_kernel() {
    if (threadIdx.x < 4) g_acc[threadIdx.x] = 0.0;
}

// B[(i*21+a)][c*64 + jj*21 + k] = (3c+jj < i) ? J[i][3c+jj][a][k] : 0  (bf16)
__global__ void build_B_kernel(const float* __restrict__ J) {
    const int n = blockIdx.x;                 // 0..KN-1
    const int i = n / Qd, a = n % Qd;
    const int nch_row = chunk_bound_for_tile(n >> 7);
    const int nquads = nch_row * (KC / 4);
    const float* Jia = J + (size_t)i * Lseq * (Qd * Qd) + (size_t)a * Qd; // + j*441 + k
    __nv_bfloat16* brow = g_B + (size_t)n * K2;
    float local = 0.f;
    for (int u = threadIdx.x; u < nquads; u += blockDim.x) {
        int kk = u * 4;
        int c = kk >> 6, off = kk & 63;
        unsigned short o[4];
        #pragma unroll
        for (int e = 0; e < 4; e++) {
            int col = off + e;
            int jj = (col >= 42) ? 2 : ((col >= 21) ? 1 : 0);
            int k = col - jj * 21;            // k == 21 only at pad col 63
            int j = 3 * c + jj;
            float v = 0.f;
            if (k < Qd && j < i) v = Jia[(size_t)j * (Qd * Qd) + k];
            o[e] = __bfloat16_as_ushort(__float2bfloat16(v));
            local += v * v;
        }
        uint2 pack;
        pack.x = (uint32_t)o[0] | ((uint32_t)o[1] << 16);
        pack.y = (uint32_t)o[2] | ((uint32_t)o[3] << 16);
        *(uint2*)(brow + kk) = pack;
    }
    double t = block_sum((double)local);
    if (threadIdx.x == 0) atomicAdd(&g_acc[2], t);
}

__global__ void stats_kernel(const float* __restrict__ w, const float* __restrict__ h) {
    double lw = 0.0, lh = 0.0;
    for (int i = blockIdx.x * blockDim.x + threadIdx.x; i < Mseq; i += gridDim.x * blockDim.x)
        lw += (double)w[i];
    for (int i = blockIdx.x * blockDim.x + threadIdx.x; i < KN; i += gridDim.x * blockDim.x) {
        float v = h[i];
        lh += (double)v * (double)v;
    }
    double tw = block_sum(lw);
    if (threadIdx.x == 0) atomicAdd(&g_acc[0], tw);
    double th = block_sum(lh);
    if (threadIdx.x == 0) atomicAdd(&g_acc[3], th);
}

// ---------------- GEMM: contrib = H(one-hot) * B^T via mma.sync ----------------
// A operand is never materialized: fragments are computed from one-hot bitmasks.
#define AROW 144                 // bytes per smem B tile row (64 bf16 + 8 pad)
#define TILE_BYTES (MT * AROW)   // 18432
#define OFF_B0 0                 // 3-stage ring
#define OFF_POS (3 * TILE_BYTES) // 55296
#define POS_STRIDE (NCH2 * 4)    // 340 bytes per row
#define SMEM_BYTES (OFF_POS + MT * POS_STRIDE)   // 98816

__global__ void __launch_bounds__(128, 2) gemm_kernel(const int* __restrict__ seqs) {
    extern __shared__ char smem[];
    const uint32_t sb = smem_u32(smem);
    const int tid = threadIdx.x, wid = tid >> 5, lane = tid & 31;
    const int n0 = blockIdx.x * NT, m0 = blockIdx.y * MT;
    const int mw = wid >> 1, nw = wid & 1;       // warp grid: 2 (m) x 2 (n), 64x64 tiles

    // ---- prologue 1: coalesced seqs -> u8 cache (staged in B ring area, temp)
    for (int u = tid; u < (MT * Lseq) / 4; u += 128) {
        int4 v = ((const int4*)seqs)[(size_t)m0 * (Lseq / 4) + u];
        uchar4 pc;
        pc.x = (unsigned char)v.x; pc.y = (unsigned char)v.y;
        pc.z = (unsigned char)v.z; pc.w = (unsigned char)v.w;
        *(uchar4*)(smem + OFF_B0 + u * 4) = pc;
    }
    __syncthreads();
    // ---- prologue 2: thread t builds packed one-hot column positions for row t
    {
        const unsigned char* sr = (const unsigned char*)(smem + OFF_B0 + tid * Lseq);
        uint32_t* pw = (uint32_t*)(smem + OFF_POS + tid * POS_STRIDE);
        #pragma unroll 5
        for (int c = 0; c < NCH2; c++) {
            uint32_t p0 = sr[3 * c], p1 = sr[3 * c + 1], p2 = sr[3 * c + 2];
            pw[c] = p0 | ((p1 + 21u) << 8) | ((p2 + 42u) << 16);
        }
    }
    __syncthreads();   // posw ready; B ring area free to overwrite

    const int nch = chunk_bound_for_tile(blockIdx.x);
    const __nv_bfloat16* gB0 = g_B + (size_t)n0 * K2;
    const int brow = tid >> 3, bseg = tid & 7;   // B copy mapping: 8x 16B per thread

    // issue copies for chunks 0 and 1 (nch >= 2 always)
    #pragma unroll
    for (int pc = 0; pc < 2; pc++) {
        const __nv_bfloat16* gp = gB0 + (size_t)pc * KC;
        const uint32_t bdst = sb + OFF_B0 + pc * TILE_BYTES;
        #pragma unroll
        for (int q = 0; q < 8; q++) {
            int r = brow + q * 16;
            CP_ASYNC16(bdst + r * AROW + bseg * 16, gp + (size_t)r * K2 + bseg * 8);
        }
        CP_COMMIT();
    }

    // per-lane ldmatrix address for B (64x64 warp tile, N rows x K cols)
    const uint32_t bLane = (uint32_t)((nw * 64 + (lane & 7) + ((lane >> 4) << 3)) * AROW +
                                      ((lane >> 3) & 1) * 16);
    const uint32_t c0 = (lane & 3) * 2;
    const int rbase = mw * 64 + (lane >> 2);

    float acc[4][8][4];
    #pragma unroll
    for (int mt = 0; mt < 4; mt++)
        #pragma unroll
        for (int n8 = 0; n8 < 8; n8++)
            #pragma unroll
            for (int r = 0; r < 4; r++) acc[mt][n8][r] = 0.f;

    int stage = 0;
    for (int c = 0; c < nch; c++) {
        CP_WAIT1();            // chunk c's copy complete (this thread)
        __syncthreads();       // visible to all; all warps done with stage (c-1)%3
        // issue copy for chunk c+2 into the just-freed stage
        {
            const int s2 = (stage + 2 >= 3) ? stage - 1 : stage + 2;
            if (c + 2 < nch) {
                const __nv_bfloat16* gp = gB0 + (size_t)(c + 2) * KC;
                const uint32_t bdst = sb + OFF_B0 + s2 * TILE_BYTES;
                #pragma unroll
                for (int q = 0; q < 8; q++) {
                    int r = brow + q * 16;
                    CP_ASYNC16(bdst + r * AROW + bseg * 16, gp + (size_t)r * K2 + bseg * 8);
                }
            }
            CP_COMMIT();       // commit (possibly empty) to keep group count uniform
        }

        // build 8 one-hot masks for this chunk (rows rbase + mt*16 + {0,8})
        uint32_t emlo[8], emhi[8];
        #pragma unroll
        for (int mt = 0; mt < 4; mt++) {
            #pragma unroll
            for (int hh = 0; hh < 2; hh++) {
                const int r = rbase + mt * 16 + hh * 8;
                uint32_t p = *(const uint32_t*)(smem + OFF_POS + r * POS_STRIDE + c * 4);
                uint64_t mask = (1ULL << (p & 0x3Fu)) | (1ULL << ((p >> 8) & 0x3Fu)) |
                                (1ULL << ((p >> 16) & 0x3Fu));
                uint64_t em = mask >> c0;
                emlo[mt * 2 + hh] = (uint32_t)em;
                emhi[mt * 2 + hh] = (uint32_t)(em >> 32);
            }
        }

        const uint32_t bBuf = sb + OFF_B0 + stage * TILE_BYTES + bLane;
        // B register double buffer across kt
        uint32_t b[2][4][4];
        #pragma unroll
        for (int nt = 0; nt < 4; nt++)
            LDSM_X4(b[0][nt][0], b[0][nt][1], b[0][nt][2], b[0][nt][3],
                    bBuf + nt * 16 * AROW);
        #pragma unroll
        for (int kt = 0; kt < 4; kt++) {
            const int cur = kt & 1, nxt = cur ^ 1;
            if (kt < 3) {
                #pragma unroll
                for (int nt = 0; nt < 4; nt++)
                    LDSM_X4(b[nxt][nt][0], b[nxt][nt][1], b[nxt][nt][2], b[nxt][nt][3],
                            bBuf + nt * 16 * AROW + (kt + 1) * 32);
            }
            #pragma unroll
            for (int mt = 0; mt < 4; mt++) {
                const uint32_t el = emlo[mt * 2], eh = emhi[mt * 2];
                const uint32_t fl = emlo[mt * 2 + 1], fh = emhi[mt * 2 + 1];
                const uint32_t e = (kt == 0) ? el : (kt == 1) ? (el >> 16)
                                 : (kt == 2) ? eh : (eh >> 16);
                const uint32_t f = (kt == 0) ? fl : (kt == 1) ? (fl >> 16)
                                 : (kt == 2) ? fh : (fh >> 16);
                uint32_t av[4];
                av[0] = (e & 1u) * 0x3F80u + (e & 2u) * 0x1FC00000u;
                av[1] = (f & 1u) * 0x3F80u + (f & 2u) * 0x1FC00000u;
                av[2] = ((e >> 8) & 1u) * 0x3F80u + ((e >> 8) & 2u) * 0x1FC00000u;
                av[3] = ((f >> 8) & 1u) * 0x3F80u + ((f >> 8) & 2u) * 0x1FC00000u;
                #pragma unroll
                for (int n8 = 0; n8 < 8; n8++) {
                    const uint32_t* bp = b[cur][n8 >> 1];
                    MMA16816(acc[mt][n8], av, bp[(n8 & 1) * 2], bp[(n8 & 1) * 2 + 1]);
                }
            }
        }
        stage = (stage + 1 >= 3) ? 0 : stage + 1;
    }

    // ---- epilogue: registers -> g_contrib
    const int rr = lane >> 2, cc = (lane & 3) * 2;
    #pragma unroll
    for (int mt = 0; mt < 4; mt++) {
        const int row0 = m0 + mw * 64 + mt * 16 + rr;
        #pragma unroll
        for (int n8 = 0; n8 < 8; n8++) {
            const int col = n0 + nw * 64 + n8 * 8 + cc;
            float2 lo = make_float2(acc[mt][n8][0], acc[mt][n8][1]);
            float2 hi = make_float2(acc[mt][n8][2], acc[mt][n8][3]);
            *(float2*)(g_contrib + (size_t)row0 * KN + col) = lo;
            *(float2*)(g_contrib + (size_t)(row0 + 8) * KN + col) = hi;
        }
    }
}

// ---------------- softmax / NLL ----------------
__global__ void nll_kernel(const int* __restrict__ seqs, const float* __restrict__ w,
                           const float* __restrict__ h) {
    double local = 0.0;
    const int total = Mseq * Lseq;
    for (int idx = blockIdx.x * blockDim.x + threadIdx.x; idx < total;
         idx += gridDim.x * blockDim.x) {
        const int b = idx >> 8, i = idx & 255;
        const float* cp = g_contrib + (size_t)b * KN + i * Qd;
        const float* hp = h + i * Qd;
        float lg[Qd];
        float mx = -1e30f;
        #pragma unroll
        for (int a = 0; a < Qd; a++) {
            lg[a] = hp[a] + cp[a];
            mx = fmaxf(mx, lg[a]);
        }
        float s = 0.f;
        #pragma unroll
        for (int a = 0; a < Qd; a++) s += expf(lg[a] - mx);
        const int sym = seqs[idx];   // idx == b*L + i
        const float ll = lg[sym] - mx - logf(s);
        local += (double)w[b] * (double)ll;
    }
    double t = block_sum(local);
    if (threadIdx.x == 0) atomicAdd(&g_acc[1], t);
}

__global__ void finalize_kernel(float* out, int out_size) {
    double wsum = g_acc[0];
    if (wsum < 1e-12) wsum = 1e-12;
    double nll = -g_acc[1] / wsum;
    double reg = 0.5e-4 * g_acc[2] + 0.5e-6 * g_acc[3];
    out[0] = (float)(nll + reg);
    if (out_size > 1) out[1] = (float)nll;
    if (out_size > 2) out[2] = (float)reg;
}

// ---------------- launch ----------------
extern "C" void kernel_launch(void* const* d_in, const int* in_sizes, int n_in,
                              void* d_out, int out_size) {
    const int*   seqs = (const int*)d_in[0];
    const float* w    = (const float*)d_in[1];
    const float* h    = (const float*)d_in[2];
    const float* J    = (const float*)d_in[3];
    float* out = (float*)d_out;

    zero_acc_kernel<<<1, 32>>>();
    build_B_kernel<<<KN, 256>>>(J);
    stats_kernel<<<64, 256>>>(w, h);

    cudaFuncSetAttribute(gemm_kernel, cudaFuncAttributeMaxDynamicSharedMemorySize, SMEM_BYTES);
    gemm_kernel<<<dim3(NTILES, MTILES), 128, SMEM_BYTES>>>(seqs);

    nll_kernel<<<2048, 256>>>(seqs, w, h);
    finalize_kernel<<<1, 1>>>(out, out_size);
}

// round 7
// speedup vs baseline: 1.5852x; 1.5852x over previous
#include <cuda_runtime.h>
#include <cuda_bf16.h>
#include <cstdint>

#define Lseq 256
#define Qd   21
#define Mseq 8192
#define KN   5376           // L*Q (output N dimension)
#define KNP  5440           // padded g_B rows (last tile reads 128 rows from n0=5292)
#define MT   128
#define NTL  126            // logical N per tile = 6 complete i-groups
#define GRP  6              // i-groups per tile
#define KC   64             // K chunk width: 3 j's * 21 + 1 pad col
#define NCH2 85             // max chunks (j up to 254)
#define K2   (NCH2 * KC)    // 5440 padded K extent of B
#define NTILES 43           // ceil(256/6) i-group tiles
#define MTILES (Mseq / MT)  // 64

// ---------------- device scratch ----------------
__device__ __nv_bfloat16 g_B[(size_t)KNP * K2];   // B[(i,a)][c*64 + jj*21 + k], causal-masked
__device__ double        g_acc[4];                // 0: wsum 1: sum w*ll 2: sum Jm^2 3: sum h^2

// ---------------- helpers ----------------
__device__ __forceinline__ uint32_t smem_u32(const void* p) {
    uint32_t r;
    asm("{ .reg .u64 t; cvta.to.shared.u64 t, %1; cvt.u32.u64 %0, t; }" : "=r"(r) : "l"(p));
    return r;
}
__device__ __forceinline__ double block_sum(double v) {
    __shared__ double sh[32];
    int lane = threadIdx.x & 31, w = threadIdx.x >> 5;
    #pragma unroll
    for (int o = 16; o; o >>= 1) v += __shfl_down_sync(0xffffffffu, v, o);
    if (lane == 0) sh[w] = v;
    __syncthreads();
    double r = 0.0;
    if (w == 0) {
        int nw = blockDim.x >> 5;
        r = (lane < nw) ? sh[lane] : 0.0;
        #pragma unroll
        for (int o = 16; o; o >>= 1) r += __shfl_down_sync(0xffffffffu, r, o);
    }
    __syncthreads();
    return r;
}

#define LDSM_X4(r0, r1, r2, r3, addr)                                            \
    asm volatile("ldmatrix.sync.aligned.m8n8.x4.shared.b16 {%0,%1,%2,%3}, [%4];" \
                 : "=r"(r0), "=r"(r1), "=r"(r2), "=r"(r3) : "r"(addr))

#define MMA16816(d, a, b0, b1)                                                          \
    asm volatile("mma.sync.aligned.m16n8k16.row.col.f32.bf16.bf16.f32 "                 \
                 "{%0,%1,%2,%3},{%4,%5,%6,%7},{%8,%9},{%0,%1,%2,%3};"                   \
                 : "+f"(d[0]), "+f"(d[1]), "+f"(d[2]), "+f"(d[3])                       \
                 : "r"(a[0]), "r"(a[1]), "r"(a[2]), "r"(a[3]), "r"(b0), "r"(b1))

#define CP_ASYNC16(dst, src)                                                             \
    asm volatile("cp.async.cg.shared.global [%0], [%1], 16;" :: "r"(dst), "l"(src))
#define CP_COMMIT() asm volatile("cp.async.commit_group;" ::: "memory")
#define CP_WAIT0()  asm volatile("cp.async.wait_group 0;" ::: "memory")

// chunks needed by tile t (covers i = 6t..6t+5): ceil((6t+5)/3) = 2t+2, capped.
__device__ __forceinline__ int chunk_bound_tile(int t) {
    int nch = 2 * t + 2;
    return nch > NCH2 ? NCH2 : nch;
}

// ---------------- small kernels ----------------
__global__ void zero_acc_kernel() {
    if (threadIdx.x < 4) g_acc[threadIdx.x] = 0.0;
}

// B[(i*21+a)][c*64 + jj*21 + k] = (3c+jj < i) ? J[i][3c+jj][a][k] : 0  (bf16)
// Block 0 additionally accumulates the w-sum and h^2 stats.
__global__ void build_B_kernel(const float* __restrict__ J, const float* __restrict__ w,
                               const float* __restrict__ h) {
    const int n = blockIdx.x;                 // 0..KN-1
    const int i = n / Qd, a = n % Qd;
    const int nch_row = chunk_bound_tile((i / GRP) < (NTILES - 1) ? (i / GRP) : (NTILES - 1));
    const int nquads = nch_row * (KC / 4);
    const float* Jia = J + (size_t)i * Lseq * (Qd * Qd) + (size_t)a * Qd; // + j*441 + k
    __nv_bfloat16* brow = g_B + (size_t)n * K2;
    float local = 0.f;
    for (int u = threadIdx.x; u < nquads; u += blockDim.x) {
        int kk = u * 4;
        int c = kk >> 6, off = kk & 63;
        unsigned short o[4];
        #pragma unroll
        for (int e = 0; e < 4; e++) {
            int col = off + e;
            int jj = (col >= 42) ? 2 : ((col >= 21) ? 1 : 0);
            int k = col - jj * 21;            // k == 21 only at pad col 63
            int j = 3 * c + jj;
            float v = 0.f;
            if (k < Qd && j < i) v = Jia[(size_t)j * (Qd * Qd) + k];
            o[e] = __bfloat16_as_ushort(__float2bfloat16(v));
            local += v * v;
        }
        uint2 pack;
        pack.x = (uint32_t)o[0] | ((uint32_t)o[1] << 16);
        pack.y = (uint32_t)o[2] | ((uint32_t)o[3] << 16);
        *(uint2*)(brow + kk) = pack;
    }
    double t = block_sum((double)local);
    if (threadIdx.x == 0) atomicAdd(&g_acc[2], t);
    if (blockIdx.x == 0) {
        double lw = 0.0, lh = 0.0;
        for (int u = threadIdx.x; u < Mseq; u += blockDim.x) lw += (double)w[u];
        for (int u = threadIdx.x; u < KN; u += blockDim.x) {
            float v = h[u];
            lh += (double)v * (double)v;
        }
        double tw = block_sum(lw);
        if (threadIdx.x == 0) atomicAdd(&g_acc[0], tw);
        double th = block_sum(lh);
        if (threadIdx.x == 0) atomicAdd(&g_acc[3], th);
    }
}

// ---------------- fused GEMM + NLL ----------------
#define AROW 144                 // bytes per smem tile row (64 bf16 + 8 pad)
#define TILE_BYTES (MT * AROW)   // 18432
#define OFF_A0 0
#define OFF_A1 (OFF_A0 + TILE_BYTES)
#define OFF_B0 (OFF_A1 + TILE_BYTES)
#define OFF_B1 (OFF_B0 + TILE_BYTES)
#define OFF_SEQ (OFF_B1 + TILE_BYTES)          // 73728
#define SEQ_STRIDE 260
#define DSTRIDE 130                            // floats per staged-D row (pad vs 128)
#define SMEM_BYTES (OFF_SEQ + MT * SEQ_STRIDE) // 107008 (D stage 128*130*4=66560 overlays A/B)

// branchless one-hot maintenance: clear chunk c_clear's 3 ones, set chunk c_set's 3.
__device__ __forceinline__ void fill_A_row(char* abase, const unsigned char* srow,
                                           int row, int c_clear, int c_set) {
    char* rp = abase + row * AROW;
    if (c_clear >= 0) {
        const int j0 = 3 * c_clear;
        #pragma unroll
        for (int jj = 0; jj < 3; jj++) {
            int col = jj * Qd + (int)srow[j0 + jj];
            *(__nv_bfloat16*)(rp + col * 2) = __nv_bfloat16(0.f);
        }
    }
    {
        const int j0 = 3 * c_set;
        const __nv_bfloat16 one = __float2bfloat16(1.0f);
        #pragma unroll
        for (int jj = 0; jj < 3; jj++) {
            int col = jj * Qd + (int)srow[j0 + jj];
            *(__nv_bfloat16*)(rp + col * 2) = one;
        }
    }
}

__global__ void __launch_bounds__(128, 2) gemm_kernel(const int* __restrict__ seqs,
                                                      const float* __restrict__ w,
                                                      const float* __restrict__ h) {
    extern __shared__ char smem[];
    const uint32_t sb = smem_u32(smem);
    const int tid = threadIdx.x, wid = tid >> 5, lane = tid & 31;
    const int tilex = blockIdx.x;                // i-group tile: i in [6*tilex, 6*tilex+6)
    const int n0 = tilex * NTL;                  // first B row (col of contrib)
    const int m0 = blockIdx.y * MT;
    const int mw = wid >> 1, nw = wid & 1;       // warp grid: 2 (m) x 2 (n), 64x64 tiles

    // ---- prologue: zero A buffers, cache seqs as u8
    {
        uint4 z = make_uint4(0, 0, 0, 0);
        #pragma unroll
        for (int q = 0; q < 18; q++)
            *(uint4*)(smem + OFF_A0 + (tid + q * 128) * 16) = z;  // 2*18432B
        for (int u = tid; u < (MT * Lseq) / 4; u += 128) {
            int4 v = ((const int4*)seqs)[(size_t)m0 * (Lseq / 4) + u];
            int row = u >> 6, col = (u & 63) * 4;
            uchar4 pc;
            pc.x = (unsigned char)v.x; pc.y = (unsigned char)v.y;
            pc.z = (unsigned char)v.z; pc.w = (unsigned char)v.w;
            *(uchar4*)(smem + OFF_SEQ + row * SEQ_STRIDE + col) = pc;
        }
    }
    __syncthreads();

    const int nch = chunk_bound_tile(tilex);     // >= 2
    const __nv_bfloat16* gB0 = g_B + (size_t)n0 * K2;

    // B copy mapping: 8 cp.async(16B) per thread per chunk; 8 lanes per row.
    const int brow = tid >> 3, bseg = tid & 7;

    // chunk 0: cp.async B + fill A
    {
        #pragma unroll
        for (int q = 0; q < 8; q++) {
            int r = brow + q * 16;
            CP_ASYNC16(sb + OFF_B0 + r * AROW + bseg * 16,
                       gB0 + (size_t)r * K2 + bseg * 8);
        }
        CP_COMMIT();
        fill_A_row(smem + OFF_A0, (const unsigned char*)(smem + OFF_SEQ + tid * SEQ_STRIDE),
                   tid, -1, 0);
        CP_WAIT0();
    }
    __syncthreads();

    // per-lane ldmatrix address pieces (64x64 warp tile)
    const uint32_t aLane = (uint32_t)((mw * 64 + (lane & 15)) * AROW + (lane >> 4) * 16);
    const uint32_t bLane = (uint32_t)((nw * 64 + (lane & 7) + ((lane >> 4) << 3)) * AROW +
                                      ((lane >> 3) & 1) * 16);

    float acc[4][8][4];
    #pragma unroll
    for (int mt = 0; mt < 4; mt++)
        #pragma unroll
        for (int n8 = 0; n8 < 8; n8++)
            #pragma unroll
            for (int r = 0; r < 4; r++) acc[mt][n8][r] = 0.f;

    for (int c = 0; c < nch; c++) {
        const int s = c & 1;
        const bool more = (c + 1 < nch);
        // issue next B copy first (drains under fill+MMA), then prep next A
        if (more) {
            const __nv_bfloat16* gp = gB0 + (size_t)(c + 1) * KC;
            const uint32_t bdst = sb + (s ? OFF_B0 : OFF_B1);
            #pragma unroll
            for (int q = 0; q < 8; q++) {
                int r = brow + q * 16;
                CP_ASYNC16(bdst + r * AROW + bseg * 16, gp + (size_t)r * K2 + bseg * 8);
            }
            CP_COMMIT();
            fill_A_row(smem + (s ? OFF_A0 : OFF_A1),
                       (const unsigned char*)(smem + OFF_SEQ + tid * SEQ_STRIDE),
                       tid, c - 1, c + 1);
        }

        const uint32_t aBuf = sb + (s ? OFF_A1 : OFF_A0) + aLane;
        const uint32_t bBuf = sb + (s ? OFF_B1 : OFF_B0) + bLane;

        // register-double-buffered kt pipeline
        uint32_t a[2][4][4], b[2][4][4];
        #pragma unroll
        for (int mt = 0; mt < 4; mt++)
            LDSM_X4(a[0][mt][0], a[0][mt][1], a[0][mt][2], a[0][mt][3],
                    aBuf + mt * 16 * AROW);
        #pragma unroll
        for (int nt = 0; nt < 4; nt++)
            LDSM_X4(b[0][nt][0], b[0][nt][1], b[0][nt][2], b[0][nt][3],
                    bBuf + nt * 16 * AROW);
        #pragma unroll
        for (int kt = 0; kt < 4; kt++) {
            const int cur = kt & 1, nxt = cur ^ 1;
            if (kt < 3) {
                #pragma unroll
                for (int mt = 0; mt < 4; mt++)
                    LDSM_X4(a[nxt][mt][0], a[nxt][mt][1], a[nxt][mt][2], a[nxt][mt][3],
                            aBuf + mt * 16 * AROW + (kt + 1) * 32);
                #pragma unroll
                for (int nt = 0; nt < 4; nt++)
                    LDSM_X4(b[nxt][nt][0], b[nxt][nt][1], b[nxt][nt][2], b[nxt][nt][3],
                            bBuf + nt * 16 * AROW + (kt + 1) * 32);
            }
            #pragma unroll
            for (int mt = 0; mt < 4; mt++) {
                #pragma unroll
                for (int n8 = 0; n8 < 8; n8++) {
                    const uint32_t* bp = b[cur][n8 >> 1];
                    MMA16816(acc[mt][n8], a[cur][mt], bp[(n8 & 1) * 2], bp[(n8 & 1) * 2 + 1]);
                }
            }
        }

        if (more) CP_WAIT0();
        __syncthreads();
    }

    // ---- stage D tile to smem (overlays dead A/B buffers), padded stride
    {
        float* D = (float*)smem;
        const int rr = lane >> 2, cc = (lane & 3) * 2;
        #pragma unroll
        for (int mt = 0; mt < 4; mt++) {
            const int row0 = mw * 64 + mt * 16 + rr;
            #pragma unroll
            for (int n8 = 0; n8 < 8; n8++) {
                const int col = nw * 64 + n8 * 8 + cc;
                *(float2*)(D + (size_t)row0 * DSTRIDE + col) =
                    make_float2(acc[mt][n8][0], acc[mt][n8][1]);
                *(float2*)(D + (size_t)(row0 + 8) * DSTRIDE + col) =
                    make_float2(acc[mt][n8][2], acc[mt][n8][3]);
            }
        }
    }
    __syncthreads();

    // ---- fused NLL: thread tid owns batch row b = m0 + tid (6 i-groups)
    {
        const float wb = w[m0 + tid];
        const unsigned char* srow = (const unsigned char*)(smem + OFF_SEQ + tid * SEQ_STRIDE);
        const float* Drow = (const float*)smem + (size_t)tid * DSTRIDE;
        float sum_ll = 0.f;
        #pragma unroll
        for (int g = 0; g < GRP; g++) {
            const int i = GRP * tilex + g;
            if (i < Lseq) {
                const float* hp = h + i * Qd;
                float lg[Qd];
                float mx = -1e30f;
                #pragma unroll
                for (int a = 0; a < Qd; a++) {
                    lg[a] = hp[a] + Drow[g * Qd + a];
                    mx = fmaxf(mx, lg[a]);
                }
                float sden = 0.f;
                #pragma unroll
                for (int a = 0; a < Qd; a++) sden += expf(lg[a] - mx);
                const int sym = srow[i];
                sum_ll += lg[sym] - mx - logf(sden);
            }
        }
        double t = block_sum((double)wb * (double)sum_ll);
        if (tid == 0) atomicAdd(&g_acc[1], t);
    }
}

__global__ void finalize_kernel(float* out, int out_size) {
    double wsum = g_acc[0];
    if (wsum < 1e-12) wsum = 1e-12;
    double nll = -g_acc[1] / wsum;
    double reg = 0.5e-4 * g_acc[2] + 0.5e-6 * g_acc[3];
    out[0] = (float)(nll + reg);
    if (out_size > 1) out[1] = (float)nll;
    if (out_size > 2) out[2] = (float)reg;
}

// ---------------- launch ----------------
extern "C" void kernel_launch(void* const* d_in, const int* in_sizes, int n_in,
                              void* d_out, int out_size) {
    const int*   seqs = (const int*)d_in[0];
    const float* w    = (const float*)d_in[1];
    const float* h    = (const float*)d_in[2];
    const float* J    = (const float*)d_in[3];
    float* out = (float*)d_out;

    zero_acc_kernel<<<1, 32>>>();
    build_B_kernel<<<KN, 256>>>(J, w, h);

    cudaFuncSetAttribute(gemm_kernel, cudaFuncAttributeMaxDynamicSharedMemorySize, SMEM_BYTES);
    gemm_kernel<<<dim3(NTILES, MTILES), 128, SMEM_BYTES>>>(seqs, w, h);

    finalize_kernel<<<1, 1>>>(out, out_size);
}